// round 8
// baseline (speedup 1.0000x reference)
#include <cuda_runtime.h>
#include <cuda_fp16.h>

#define N_NODES 100000
#define N_FEAT  256
#define OUT_DIM 128
#define NNZ_X   1600000
#define NNZ_A   1600000

#define SCAN_CHUNK 2048          // 256 threads x 8 elems
#define SCAN_NBLK  ((N_NODES + SCAN_CHUNK - 1) / SCAN_CHUNK)   // 49

// ---------------- device scratch (device-code references only) ----------------
__device__ uint4  g_xw4[(size_t)N_NODES * 16];   // xw fp16: row = 256 B = 16 uint4
__device__ __half g_W16[N_FEAT * OUT_DIM];       // fp16 copy of W (64 KB)

__device__ int   g_cnt_f[N_NODES];
__device__ int   g_cnt_a[N_NODES];
__device__ int   g_off_f[N_NODES];
__device__ int   g_off_a[N_NODES];
__device__ int   g_cur_f[N_NODES];
__device__ int   g_cur_a[N_NODES];

// decoupled-lookback state, PACKED: high32 = flag (0=invalid,1=agg,2=inclusive)
__device__ unsigned long long g_scan_pack[2][SCAN_NBLK];

// packed (col, val-bits) pairs, row-sorted
__device__ int2  g_pair_f[NNZ_X];
__device__ int2  g_pair_a[NNZ_A];

// ---------------------------------------------------------------------------
// 0) zero histograms + reset scan state + convert W to fp16
// ---------------------------------------------------------------------------
__global__ void init_kernel(const float* __restrict__ W) {
    int i = blockIdx.x * blockDim.x + threadIdx.x;
    if (i < N_NODES) { g_cnt_f[i] = 0; g_cnt_a[i] = 0; }
    if (i < 2 * SCAN_NBLK) {
        g_scan_pack[i / SCAN_NBLK][i % SCAN_NBLK] = 0ULL;
    }
    if (i < N_FEAT * OUT_DIM) {
        g_W16[i] = __float2half_rn(__ldg(W + i));
    }
}

// ---------------------------------------------------------------------------
// 1) histogram both row arrays, 4 elements per thread (MLP=8 per thread)
// ---------------------------------------------------------------------------
__global__ void hist_kernel(const int* __restrict__ rows_f,
                            const int* __restrict__ rows_a) {
    int i = blockIdx.x * blockDim.x + threadIdx.x;   // i indexes groups of 4
    if (i < NNZ_X / 4) {
        int4 rf = __ldg(reinterpret_cast<const int4*>(rows_f) + i);
        atomicAdd(&g_cnt_f[rf.x], 1);
        atomicAdd(&g_cnt_f[rf.y], 1);
        atomicAdd(&g_cnt_f[rf.z], 1);
        atomicAdd(&g_cnt_f[rf.w], 1);
    }
    if (i < NNZ_A / 4) {
        int4 ra = __ldg(reinterpret_cast<const int4*>(rows_a) + i);
        atomicAdd(&g_cnt_a[ra.x], 1);
        atomicAdd(&g_cnt_a[ra.y], 1);
        atomicAdd(&g_cnt_a[ra.z], 1);
        atomicAdd(&g_cnt_a[ra.w], 1);
    }
}

// ---------------------------------------------------------------------------
// 2) single-pass exclusive scan (decoupled lookback, packed flag|value).
// ---------------------------------------------------------------------------
__global__ void scan_kernel() {
    __shared__ int s[256];
    __shared__ int s_excl;
    int arr = blockIdx.y;
    const int* cnt = (arr == 0) ? g_cnt_f : g_cnt_a;
    int* off = (arr == 0) ? g_off_f : g_off_a;
    int* cur = (arr == 0) ? g_cur_f : g_cur_a;

    int t = threadIdx.x;
    int bid = blockIdx.x;
    int base = bid * SCAN_CHUNK + t * 8;

    int local[8];
    int sum = 0;
#pragma unroll
    for (int k = 0; k < 8; k++) {
        int idx = base + k;
        local[k] = (idx < N_NODES) ? cnt[idx] : 0;
        sum += local[k];
    }
    s[t] = sum;
    __syncthreads();
    for (int d = 1; d < 256; d <<= 1) {
        int v = (t >= d) ? s[t - d] : 0;
        __syncthreads();
        s[t] += v;
        __syncthreads();
    }
    int block_total = s[255];

    if (t == 0) {
        if (bid == 0) {
            atomicExch(&g_scan_pack[arr][0],
                       (2ULL << 32) | (unsigned)block_total);
            s_excl = 0;
        } else {
            atomicExch(&g_scan_pack[arr][bid],
                       (1ULL << 32) | (unsigned)block_total);
            int running = 0;
            for (int p = bid - 1; p >= 0; p--) {
                unsigned long long pk;
                do { pk = atomicAdd(&g_scan_pack[arr][p], 0ULL); }
                while ((pk >> 32) == 0ULL);
                running += (int)(unsigned)pk;
                if ((pk >> 32) == 2ULL) break;
            }
            atomicExch(&g_scan_pack[arr][bid],
                       (2ULL << 32) | (unsigned)(running + block_total));
            s_excl = running;
        }
    }
    __syncthreads();
    int excl_blk = s_excl;

    int excl_thr = (t == 0) ? 0 : s[t - 1];
    int run = excl_blk + excl_thr;
#pragma unroll
    for (int k = 0; k < 8; k++) {
        int idx = base + k;
        if (idx < N_NODES) { off[idx] = run; cur[idx] = run; run += local[k]; }
    }
}

// ---------------------------------------------------------------------------
// 3) scatter packed (col,val) pairs, 4 nnz per thread.
//    Vector loads of rows/cols/vals; 4 independent atomics + 4 independent
//    stores in flight per thread (kills the MLP=1 latency chain).
// ---------------------------------------------------------------------------
__global__ void scatter_pairs_kernel(const int* __restrict__ rows_f,
                                     const int* __restrict__ cols_f,
                                     const float* __restrict__ vals_f,
                                     const int* __restrict__ rows_a,
                                     const int* __restrict__ cols_a,
                                     const float* __restrict__ vals_a) {
    int i = blockIdx.x * blockDim.x + threadIdx.x;   // group of 4 nnz
    const int* rows;  const int* cols;  const float* vals;
    int* cur;  int2* pair;  int ngrp;
    if (blockIdx.y == 0) {
        rows = rows_f; cols = cols_f; vals = vals_f;
        cur = g_cur_f; pair = g_pair_f; ngrp = NNZ_X / 4;
    } else {
        rows = rows_a; cols = cols_a; vals = vals_a;
        cur = g_cur_a; pair = g_pair_a; ngrp = NNZ_A / 4;
    }
    if (i >= ngrp) return;

    int4   r = __ldg(reinterpret_cast<const int4*>(rows) + i);
    int4   c = __ldg(reinterpret_cast<const int4*>(cols) + i);
    float4 v = __ldg(reinterpret_cast<const float4*>(vals) + i);

    int p0 = atomicAdd(&cur[r.x], 1);
    int p1 = atomicAdd(&cur[r.y], 1);
    int p2 = atomicAdd(&cur[r.z], 1);
    int p3 = atomicAdd(&cur[r.w], 1);

    pair[p0] = make_int2(c.x, __float_as_int(v.x));
    pair[p1] = make_int2(c.y, __float_as_int(v.y));
    pair[p2] = make_int2(c.z, __float_as_int(v.z));
    pair[p3] = make_int2(c.w, __float_as_int(v.w));
}

// ---------------------------------------------------------------------------
// 4) stage 1 gather: xw[r,:] = sum_j val[j] * W16[col[j],:]
//    half-warp per row; lane owns 8 dims; fp32 accumulate, fp16 round once.
// ---------------------------------------------------------------------------
__global__ void xw_gather_kernel() {
    int gtid = blockIdx.x * blockDim.x + threadIdx.x;
    int r    = gtid >> 4;
    int lane = gtid & 15;
    if (r >= N_NODES) return;

    int s = g_off_f[r];
    int e = g_cur_f[r];

    const uint4* W4 = reinterpret_cast<const uint4*>(g_W16);
    float a0 = 0.f, a1 = 0.f, a2 = 0.f, a3 = 0.f;
    float a4 = 0.f, a5 = 0.f, a6 = 0.f, a7 = 0.f;
#pragma unroll 4
    for (int j = s; j < e; j++) {
        int2 p = __ldg(g_pair_f + j);
        float v = __int_as_float(p.y);
        uint4 u = __ldg(W4 + (size_t)p.x * 16 + lane);
        float2 f0 = __half22float2(*reinterpret_cast<__half2*>(&u.x));
        float2 f1 = __half22float2(*reinterpret_cast<__half2*>(&u.y));
        float2 f2 = __half22float2(*reinterpret_cast<__half2*>(&u.z));
        float2 f3 = __half22float2(*reinterpret_cast<__half2*>(&u.w));
        a0 = fmaf(v, f0.x, a0);  a1 = fmaf(v, f0.y, a1);
        a2 = fmaf(v, f1.x, a2);  a3 = fmaf(v, f1.y, a3);
        a4 = fmaf(v, f2.x, a4);  a5 = fmaf(v, f2.y, a5);
        a6 = fmaf(v, f3.x, a6);  a7 = fmaf(v, f3.y, a7);
    }
    __half2 h0 = __floats2half2_rn(a0, a1);
    __half2 h1 = __floats2half2_rn(a2, a3);
    __half2 h2 = __floats2half2_rn(a4, a5);
    __half2 h3 = __floats2half2_rn(a6, a7);
    uint4 u;
    u.x = *reinterpret_cast<unsigned*>(&h0);
    u.y = *reinterpret_cast<unsigned*>(&h1);
    u.z = *reinterpret_cast<unsigned*>(&h2);
    u.w = *reinterpret_cast<unsigned*>(&h3);
    g_xw4[(size_t)r * 16 + lane] = u;
}

// ---------------------------------------------------------------------------
// 5) stage 2 gather + ReLU, half-warp per row (uint4 fp16 loads from L2).
// ---------------------------------------------------------------------------
__global__ void agg_gather_kernel(float* __restrict__ out) {
    int gtid = blockIdx.x * blockDim.x + threadIdx.x;
    int r    = gtid >> 4;
    int lane = gtid & 15;
    if (r >= N_NODES) return;

    int s = g_off_a[r];
    int e = g_cur_a[r];

    float a0 = 0.f, a1 = 0.f, a2 = 0.f, a3 = 0.f;
    float a4 = 0.f, a5 = 0.f, a6 = 0.f, a7 = 0.f;
#pragma unroll 4
    for (int j = s; j < e; j++) {
        int2 p = __ldg(g_pair_a + j);
        float v = __int_as_float(p.y);
        uint4 u = __ldg(g_xw4 + (size_t)p.x * 16 + lane);
        float2 f0 = __half22float2(*reinterpret_cast<__half2*>(&u.x));
        float2 f1 = __half22float2(*reinterpret_cast<__half2*>(&u.y));
        float2 f2 = __half22float2(*reinterpret_cast<__half2*>(&u.z));
        float2 f3 = __half22float2(*reinterpret_cast<__half2*>(&u.w));
        a0 = fmaf(v, f0.x, a0);  a1 = fmaf(v, f0.y, a1);
        a2 = fmaf(v, f1.x, a2);  a3 = fmaf(v, f1.y, a3);
        a4 = fmaf(v, f2.x, a4);  a5 = fmaf(v, f2.y, a5);
        a6 = fmaf(v, f3.x, a6);  a7 = fmaf(v, f3.y, a7);
    }
    float4 o0 = make_float4(fmaxf(a0, 0.f), fmaxf(a1, 0.f),
                            fmaxf(a2, 0.f), fmaxf(a3, 0.f));
    float4 o1 = make_float4(fmaxf(a4, 0.f), fmaxf(a5, 0.f),
                            fmaxf(a6, 0.f), fmaxf(a7, 0.f));
    float4* orow = reinterpret_cast<float4*>(out + (size_t)r * OUT_DIM);
    orow[lane * 2]     = o0;
    orow[lane * 2 + 1] = o1;
}

// ---------------------------------------------------------------------------
// metadata order: feat_rows, feat_cols, feat_vals, adj_rows, adj_cols,
//                 adj_vals, W, n_nodes
// ---------------------------------------------------------------------------
extern "C" void kernel_launch(void* const* d_in, const int* in_sizes, int n_in,
                              void* d_out, int out_size) {
    const int*   feat_rows = (const int*)d_in[0];
    const int*   feat_cols = (const int*)d_in[1];
    const float* feat_vals = (const float*)d_in[2];
    const int*   adj_rows  = (const int*)d_in[3];
    const int*   adj_cols  = (const int*)d_in[4];
    const float* adj_vals  = (const float*)d_in[5];
    const float* W         = (const float*)d_in[6];
    float* out = (float*)d_out;

    init_kernel<<<(N_NODES + 255) / 256, 256>>>(W);
    hist_kernel<<<(NNZ_X / 4 + 255) / 256, 256>>>(feat_rows, adj_rows);

    dim3 sg(SCAN_NBLK, 2);
    scan_kernel<<<sg, 256>>>();

    dim3 sc((NNZ_X / 4 + 255) / 256, 2);
    scatter_pairs_kernel<<<sc, 256>>>(feat_rows, feat_cols, feat_vals,
                                      adj_rows, adj_cols, adj_vals);

    xw_gather_kernel<<<(N_NODES * 16 + 255) / 256, 256>>>();
    agg_gather_kernel<<<(N_NODES * 16 + 255) / 256, 256>>>(out);
}

// round 9
// speedup vs baseline: 1.0259x; 1.0259x over previous
#include <cuda_runtime.h>
#include <cuda_fp16.h>

#define N_NODES 100000
#define N_FEAT  256
#define OUT_DIM 128
#define NNZ_X   1600000
#define NNZ_A   1600000

#define SCAN_CHUNK 2048          // 256 threads x 8 elems
#define SCAN_NBLK  ((N_NODES + SCAN_CHUNK - 1) / SCAN_CHUNK)   // 49

// ---------------- device scratch (device-code references only) ----------------
__device__ uint4  g_xw4[(size_t)N_NODES * 16];   // xw fp16: row = 256 B = 16 uint4
__device__ __half g_W16[N_FEAT * OUT_DIM];       // fp16 copy of W (64 KB)

__device__ int   g_cnt_f[N_NODES];
__device__ int   g_cnt_a[N_NODES];
__device__ int   g_off_f[N_NODES + 1];           // exclusive prefix; [N]=NNZ_X
__device__ int   g_off_a[N_NODES + 1];           // exclusive prefix; [N]=NNZ_A

__device__ int   g_rank_f[NNZ_X];                // within-row rank from hist pass
__device__ int   g_rank_a[NNZ_A];

// decoupled-lookback state, PACKED: high32 = flag (0=invalid,1=agg,2=inclusive)
__device__ unsigned long long g_scan_pack[2][SCAN_NBLK];

// packed (col, val-bits) pairs, row-sorted
__device__ int2  g_pair_f[NNZ_X];
__device__ int2  g_pair_a[NNZ_A];

// ---------------------------------------------------------------------------
// 0) zero histograms + reset scan state + convert W to fp16 + static totals
// ---------------------------------------------------------------------------
__global__ void init_kernel(const float* __restrict__ W) {
    int i = blockIdx.x * blockDim.x + threadIdx.x;
    if (i < N_NODES) { g_cnt_f[i] = 0; g_cnt_a[i] = 0; }
    if (i < 2 * SCAN_NBLK) {
        g_scan_pack[i / SCAN_NBLK][i % SCAN_NBLK] = 0ULL;
    }
    if (i < N_FEAT * OUT_DIM) {
        g_W16[i] = __float2half_rn(__ldg(W + i));
    }
    if (i == 0) { g_off_f[N_NODES] = NNZ_X; g_off_a[N_NODES] = NNZ_A; }
}

// ---------------------------------------------------------------------------
// 1) histogram both row arrays; KEEP the atomic return value as the
//    within-row rank (same RMW traffic as plain hist, enables atomic-free
//    scatter).
// ---------------------------------------------------------------------------
__global__ void hist_rank_kernel(const int* __restrict__ rows_f,
                                 const int* __restrict__ rows_a) {
    int i = blockIdx.x * blockDim.x + threadIdx.x;
    if (i < NNZ_X) g_rank_f[i] = atomicAdd(&g_cnt_f[__ldg(rows_f + i)], 1);
    if (i < NNZ_A) g_rank_a[i] = atomicAdd(&g_cnt_a[__ldg(rows_a + i)], 1);
}

// ---------------------------------------------------------------------------
// 2) single-pass exclusive scan (decoupled lookback, packed flag|value).
// ---------------------------------------------------------------------------
__global__ void scan_kernel() {
    __shared__ int s[256];
    __shared__ int s_excl;
    int arr = blockIdx.y;
    const int* cnt = (arr == 0) ? g_cnt_f : g_cnt_a;
    int* off = (arr == 0) ? g_off_f : g_off_a;

    int t = threadIdx.x;
    int bid = blockIdx.x;
    int base = bid * SCAN_CHUNK + t * 8;

    int local[8];
    int sum = 0;
#pragma unroll
    for (int k = 0; k < 8; k++) {
        int idx = base + k;
        local[k] = (idx < N_NODES) ? cnt[idx] : 0;
        sum += local[k];
    }
    s[t] = sum;
    __syncthreads();
    for (int d = 1; d < 256; d <<= 1) {
        int v = (t >= d) ? s[t - d] : 0;
        __syncthreads();
        s[t] += v;
        __syncthreads();
    }
    int block_total = s[255];

    if (t == 0) {
        if (bid == 0) {
            atomicExch(&g_scan_pack[arr][0],
                       (2ULL << 32) | (unsigned)block_total);
            s_excl = 0;
        } else {
            atomicExch(&g_scan_pack[arr][bid],
                       (1ULL << 32) | (unsigned)block_total);
            int running = 0;
            for (int p = bid - 1; p >= 0; p--) {
                unsigned long long pk;
                do { pk = atomicAdd(&g_scan_pack[arr][p], 0ULL); }
                while ((pk >> 32) == 0ULL);
                running += (int)(unsigned)pk;
                if ((pk >> 32) == 2ULL) break;
            }
            atomicExch(&g_scan_pack[arr][bid],
                       (2ULL << 32) | (unsigned)(running + block_total));
            s_excl = running;
        }
    }
    __syncthreads();
    int excl_blk = s_excl;

    int excl_thr = (t == 0) ? 0 : s[t - 1];
    int run = excl_blk + excl_thr;
#pragma unroll
    for (int k = 0; k < 8; k++) {
        int idx = base + k;
        if (idx < N_NODES) { off[idx] = run; run += local[k]; }
    }
}

// ---------------------------------------------------------------------------
// 3) ATOMIC-FREE scatter: pos = off[row] + rank. off reads are random but
//    hit an 800 KB L2-resident array with heavy sector reuse.
// ---------------------------------------------------------------------------
__global__ void scatter_pairs_kernel(const int* __restrict__ rows_f,
                                     const int* __restrict__ cols_f,
                                     const float* __restrict__ vals_f,
                                     const int* __restrict__ rows_a,
                                     const int* __restrict__ cols_a,
                                     const float* __restrict__ vals_a) {
    int i = blockIdx.x * blockDim.x + threadIdx.x;
    if (blockIdx.y == 0) {
        if (i >= NNZ_X) return;
        int r = __ldg(rows_f + i);
        int pos = __ldg(g_off_f + r) + g_rank_f[i];
        g_pair_f[pos] = make_int2(__ldg(cols_f + i),
                                  __float_as_int(__ldg(vals_f + i)));
    } else {
        if (i >= NNZ_A) return;
        int r = __ldg(rows_a + i);
        int pos = __ldg(g_off_a + r) + g_rank_a[i];
        g_pair_a[pos] = make_int2(__ldg(cols_a + i),
                                  __float_as_int(__ldg(vals_a + i)));
    }
}

// ---------------------------------------------------------------------------
// 4) stage 1 gather: xw[r,:] = sum_j val[j] * W16[col[j],:]
//    half-warp per row; lane owns 8 dims; fp32 accumulate, fp16 round once.
// ---------------------------------------------------------------------------
__global__ void xw_gather_kernel() {
    int gtid = blockIdx.x * blockDim.x + threadIdx.x;
    int r    = gtid >> 4;
    int lane = gtid & 15;
    if (r >= N_NODES) return;

    int s = __ldg(g_off_f + r);
    int e = __ldg(g_off_f + r + 1);

    const uint4* W4 = reinterpret_cast<const uint4*>(g_W16);
    float a0 = 0.f, a1 = 0.f, a2 = 0.f, a3 = 0.f;
    float a4 = 0.f, a5 = 0.f, a6 = 0.f, a7 = 0.f;
#pragma unroll 4
    for (int j = s; j < e; j++) {
        int2 p = __ldg(g_pair_f + j);
        float v = __int_as_float(p.y);
        uint4 u = __ldg(W4 + (size_t)p.x * 16 + lane);
        float2 f0 = __half22float2(*reinterpret_cast<__half2*>(&u.x));
        float2 f1 = __half22float2(*reinterpret_cast<__half2*>(&u.y));
        float2 f2 = __half22float2(*reinterpret_cast<__half2*>(&u.z));
        float2 f3 = __half22float2(*reinterpret_cast<__half2*>(&u.w));
        a0 = fmaf(v, f0.x, a0);  a1 = fmaf(v, f0.y, a1);
        a2 = fmaf(v, f1.x, a2);  a3 = fmaf(v, f1.y, a3);
        a4 = fmaf(v, f2.x, a4);  a5 = fmaf(v, f2.y, a5);
        a6 = fmaf(v, f3.x, a6);  a7 = fmaf(v, f3.y, a7);
    }
    __half2 h0 = __floats2half2_rn(a0, a1);
    __half2 h1 = __floats2half2_rn(a2, a3);
    __half2 h2 = __floats2half2_rn(a4, a5);
    __half2 h3 = __floats2half2_rn(a6, a7);
    uint4 u;
    u.x = *reinterpret_cast<unsigned*>(&h0);
    u.y = *reinterpret_cast<unsigned*>(&h1);
    u.z = *reinterpret_cast<unsigned*>(&h2);
    u.w = *reinterpret_cast<unsigned*>(&h3);
    g_xw4[(size_t)r * 16 + lane] = u;
}

// ---------------------------------------------------------------------------
// 5) stage 2 gather + ReLU, half-warp per row (uint4 fp16 loads from L2).
// ---------------------------------------------------------------------------
__global__ void agg_gather_kernel(float* __restrict__ out) {
    int gtid = blockIdx.x * blockDim.x + threadIdx.x;
    int r    = gtid >> 4;
    int lane = gtid & 15;
    if (r >= N_NODES) return;

    int s = __ldg(g_off_a + r);
    int e = __ldg(g_off_a + r + 1);

    float a0 = 0.f, a1 = 0.f, a2 = 0.f, a3 = 0.f;
    float a4 = 0.f, a5 = 0.f, a6 = 0.f, a7 = 0.f;
#pragma unroll 4
    for (int j = s; j < e; j++) {
        int2 p = __ldg(g_pair_a + j);
        float v = __int_as_float(p.y);
        uint4 u = __ldg(g_xw4 + (size_t)p.x * 16 + lane);
        float2 f0 = __half22float2(*reinterpret_cast<__half2*>(&u.x));
        float2 f1 = __half22float2(*reinterpret_cast<__half2*>(&u.y));
        float2 f2 = __half22float2(*reinterpret_cast<__half2*>(&u.z));
        float2 f3 = __half22float2(*reinterpret_cast<__half2*>(&u.w));
        a0 = fmaf(v, f0.x, a0);  a1 = fmaf(v, f0.y, a1);
        a2 = fmaf(v, f1.x, a2);  a3 = fmaf(v, f1.y, a3);
        a4 = fmaf(v, f2.x, a4);  a5 = fmaf(v, f2.y, a5);
        a6 = fmaf(v, f3.x, a6);  a7 = fmaf(v, f3.y, a7);
    }
    float4 o0 = make_float4(fmaxf(a0, 0.f), fmaxf(a1, 0.f),
                            fmaxf(a2, 0.f), fmaxf(a3, 0.f));
    float4 o1 = make_float4(fmaxf(a4, 0.f), fmaxf(a5, 0.f),
                            fmaxf(a6, 0.f), fmaxf(a7, 0.f));
    float4* orow = reinterpret_cast<float4*>(out + (size_t)r * OUT_DIM);
    orow[lane * 2]     = o0;
    orow[lane * 2 + 1] = o1;
}

// ---------------------------------------------------------------------------
// metadata order: feat_rows, feat_cols, feat_vals, adj_rows, adj_cols,
//                 adj_vals, W, n_nodes
// ---------------------------------------------------------------------------
extern "C" void kernel_launch(void* const* d_in, const int* in_sizes, int n_in,
                              void* d_out, int out_size) {
    const int*   feat_rows = (const int*)d_in[0];
    const int*   feat_cols = (const int*)d_in[1];
    const float* feat_vals = (const float*)d_in[2];
    const int*   adj_rows  = (const int*)d_in[3];
    const int*   adj_cols  = (const int*)d_in[4];
    const float* adj_vals  = (const float*)d_in[5];
    const float* W         = (const float*)d_in[6];
    float* out = (float*)d_out;

    init_kernel<<<(N_NODES + 255) / 256, 256>>>(W);
    hist_rank_kernel<<<(NNZ_X + 255) / 256, 256>>>(feat_rows, adj_rows);

    dim3 sg(SCAN_NBLK, 2);
    scan_kernel<<<sg, 256>>>();

    dim3 sc((NNZ_X + 255) / 256, 2);
    scatter_pairs_kernel<<<sc, 256>>>(feat_rows, feat_cols, feat_vals,
                                      adj_rows, adj_cols, adj_vals);

    xw_gather_kernel<<<(N_NODES * 16 + 255) / 256, 256>>>();
    agg_gather_kernel<<<(N_NODES * 16 + 255) / 256, 256>>>(out);
}

// round 10
// speedup vs baseline: 1.0262x; 1.0002x over previous
#include <cuda_runtime.h>
#include <cuda_fp16.h>

#define N_NODES 100000
#define N_FEAT  256
#define OUT_DIM 128
#define NNZ_X   1600000
#define NNZ_A   1600000

#define SCAN_CHUNK 2048          // 256 threads x 8 elems
#define SCAN_NBLK  ((N_NODES + SCAN_CHUNK - 1) / SCAN_CHUNK)   // 49

// ---------------- device scratch (device-code references only) ----------------
__device__ uint4  g_xw4[(size_t)N_NODES * 16];   // xw fp16: row = 256 B = 16 uint4
__device__ __half g_W16[N_FEAT * OUT_DIM];       // fp16 copy of W (64 KB)

__device__ int   g_cnt_f[N_NODES];
__device__ int   g_cnt_a[N_NODES];
__device__ int   g_off_f[N_NODES + 1];           // exclusive prefix; [N]=NNZ_X
__device__ int   g_off_a[N_NODES + 1];           // exclusive prefix; [N]=NNZ_A

// packed (row<<15 | rank): row 17 bits (<131072), rank 15 bits (max deg ~50)
__device__ unsigned g_rr_f[NNZ_X];
__device__ unsigned g_rr_a[NNZ_A];

// decoupled-lookback state, PACKED: high32 = flag (0=invalid,1=agg,2=inclusive)
__device__ unsigned long long g_scan_pack[2][SCAN_NBLK];

// packed (col, val-bits) pairs, row-sorted
__device__ int2  g_pair_f[NNZ_X];
__device__ int2  g_pair_a[NNZ_A];

// ---------------------------------------------------------------------------
// 0) zero histograms + reset scan state + convert W to fp16 + static totals
// ---------------------------------------------------------------------------
__global__ void init_kernel(const float* __restrict__ W) {
    int i = blockIdx.x * blockDim.x + threadIdx.x;
    if (i < N_NODES) { g_cnt_f[i] = 0; g_cnt_a[i] = 0; }
    if (i < 2 * SCAN_NBLK) {
        g_scan_pack[i / SCAN_NBLK][i % SCAN_NBLK] = 0ULL;
    }
    if (i < N_FEAT * OUT_DIM) {
        g_W16[i] = __float2half_rn(__ldg(W + i));
    }
    if (i == 0) { g_off_f[N_NODES] = NNZ_X; g_off_a[N_NODES] = NNZ_A; }
}

// ---------------------------------------------------------------------------
// 1) histogram; publish packed (row<<15 | rank) so the scatter needs only ONE
//    coalesced stream instead of rows + rank.
// ---------------------------------------------------------------------------
__global__ void hist_rank_kernel(const int* __restrict__ rows_f,
                                 const int* __restrict__ rows_a) {
    int i = blockIdx.x * blockDim.x + threadIdx.x;
    if (i < NNZ_X) {
        unsigned r = (unsigned)__ldg(rows_f + i);
        unsigned rk = (unsigned)atomicAdd(&g_cnt_f[r], 1);
        g_rr_f[i] = (r << 15) | rk;
    }
    if (i < NNZ_A) {
        unsigned r = (unsigned)__ldg(rows_a + i);
        unsigned rk = (unsigned)atomicAdd(&g_cnt_a[r], 1);
        g_rr_a[i] = (r << 15) | rk;
    }
}

// ---------------------------------------------------------------------------
// 2) single-pass exclusive scan (decoupled lookback, packed flag|value).
// ---------------------------------------------------------------------------
__global__ void scan_kernel() {
    __shared__ int s[256];
    __shared__ int s_excl;
    int arr = blockIdx.y;
    const int* cnt = (arr == 0) ? g_cnt_f : g_cnt_a;
    int* off = (arr == 0) ? g_off_f : g_off_a;

    int t = threadIdx.x;
    int bid = blockIdx.x;
    int base = bid * SCAN_CHUNK + t * 8;

    int local[8];
    int sum = 0;
#pragma unroll
    for (int k = 0; k < 8; k++) {
        int idx = base + k;
        local[k] = (idx < N_NODES) ? cnt[idx] : 0;
        sum += local[k];
    }
    s[t] = sum;
    __syncthreads();
    for (int d = 1; d < 256; d <<= 1) {
        int v = (t >= d) ? s[t - d] : 0;
        __syncthreads();
        s[t] += v;
        __syncthreads();
    }
    int block_total = s[255];

    if (t == 0) {
        if (bid == 0) {
            atomicExch(&g_scan_pack[arr][0],
                       (2ULL << 32) | (unsigned)block_total);
            s_excl = 0;
        } else {
            atomicExch(&g_scan_pack[arr][bid],
                       (1ULL << 32) | (unsigned)block_total);
            int running = 0;
            for (int p = bid - 1; p >= 0; p--) {
                unsigned long long pk;
                do { pk = atomicAdd(&g_scan_pack[arr][p], 0ULL); }
                while ((pk >> 32) == 0ULL);
                running += (int)(unsigned)pk;
                if ((pk >> 32) == 2ULL) break;
            }
            atomicExch(&g_scan_pack[arr][bid],
                       (2ULL << 32) | (unsigned)(running + block_total));
            s_excl = running;
        }
    }
    __syncthreads();
    int excl_blk = s_excl;

    int excl_thr = (t == 0) ? 0 : s[t - 1];
    int run = excl_blk + excl_thr;
#pragma unroll
    for (int k = 0; k < 8; k++) {
        int idx = base + k;
        if (idx < N_NODES) { off[idx] = run; run += local[k]; }
    }
}

// ---------------------------------------------------------------------------
// 3) ATOMIC-FREE scatter: pos = off[row] + rank from ONE packed stream.
// ---------------------------------------------------------------------------
__global__ void scatter_pairs_kernel(const int* __restrict__ cols_f,
                                     const float* __restrict__ vals_f,
                                     const int* __restrict__ cols_a,
                                     const float* __restrict__ vals_a) {
    int i = blockIdx.x * blockDim.x + threadIdx.x;
    if (blockIdx.y == 0) {
        if (i >= NNZ_X) return;
        unsigned pk = g_rr_f[i];
        int pos = __ldg(g_off_f + (pk >> 15)) + (int)(pk & 0x7FFFu);
        g_pair_f[pos] = make_int2(__ldg(cols_f + i),
                                  __float_as_int(__ldg(vals_f + i)));
    } else {
        if (i >= NNZ_A) return;
        unsigned pk = g_rr_a[i];
        int pos = __ldg(g_off_a + (pk >> 15)) + (int)(pk & 0x7FFFu);
        g_pair_a[pos] = make_int2(__ldg(cols_a + i),
                                  __float_as_int(__ldg(vals_a + i)));
    }
}

// ---------------------------------------------------------------------------
// 4) stage 1 gather: xw[r,:] = sum_j val[j] * W16[col[j],:]
//    half-warp per row; lane owns 8 dims; fp32 accumulate, fp16 round once.
// ---------------------------------------------------------------------------
__global__ void xw_gather_kernel() {
    int gtid = blockIdx.x * blockDim.x + threadIdx.x;
    int r    = gtid >> 4;
    int lane = gtid & 15;
    if (r >= N_NODES) return;

    int s = __ldg(g_off_f + r);
    int e = __ldg(g_off_f + r + 1);

    const uint4* W4 = reinterpret_cast<const uint4*>(g_W16);
    float a0 = 0.f, a1 = 0.f, a2 = 0.f, a3 = 0.f;
    float a4 = 0.f, a5 = 0.f, a6 = 0.f, a7 = 0.f;
#pragma unroll 4
    for (int j = s; j < e; j++) {
        int2 p = __ldg(g_pair_f + j);
        float v = __int_as_float(p.y);
        uint4 u = __ldg(W4 + (size_t)p.x * 16 + lane);
        float2 f0 = __half22float2(*reinterpret_cast<__half2*>(&u.x));
        float2 f1 = __half22float2(*reinterpret_cast<__half2*>(&u.y));
        float2 f2 = __half22float2(*reinterpret_cast<__half2*>(&u.z));
        float2 f3 = __half22float2(*reinterpret_cast<__half2*>(&u.w));
        a0 = fmaf(v, f0.x, a0);  a1 = fmaf(v, f0.y, a1);
        a2 = fmaf(v, f1.x, a2);  a3 = fmaf(v, f1.y, a3);
        a4 = fmaf(v, f2.x, a4);  a5 = fmaf(v, f2.y, a5);
        a6 = fmaf(v, f3.x, a6);  a7 = fmaf(v, f3.y, a7);
    }
    __half2 h0 = __floats2half2_rn(a0, a1);
    __half2 h1 = __floats2half2_rn(a2, a3);
    __half2 h2 = __floats2half2_rn(a4, a5);
    __half2 h3 = __floats2half2_rn(a6, a7);
    uint4 u;
    u.x = *reinterpret_cast<unsigned*>(&h0);
    u.y = *reinterpret_cast<unsigned*>(&h1);
    u.z = *reinterpret_cast<unsigned*>(&h2);
    u.w = *reinterpret_cast<unsigned*>(&h3);
    g_xw4[(size_t)r * 16 + lane] = u;
}

// ---------------------------------------------------------------------------
// 5) stage 2 gather + ReLU, half-warp per row (uint4 fp16 loads from L2).
// ---------------------------------------------------------------------------
__global__ void agg_gather_kernel(float* __restrict__ out) {
    int gtid = blockIdx.x * blockDim.x + threadIdx.x;
    int r    = gtid >> 4;
    int lane = gtid & 15;
    if (r >= N_NODES) return;

    int s = __ldg(g_off_a + r);
    int e = __ldg(g_off_a + r + 1);

    float a0 = 0.f, a1 = 0.f, a2 = 0.f, a3 = 0.f;
    float a4 = 0.f, a5 = 0.f, a6 = 0.f, a7 = 0.f;
#pragma unroll 4
    for (int j = s; j < e; j++) {
        int2 p = __ldg(g_pair_a + j);
        float v = __int_as_float(p.y);
        uint4 u = __ldg(g_xw4 + (size_t)p.x * 16 + lane);
        float2 f0 = __half22float2(*reinterpret_cast<__half2*>(&u.x));
        float2 f1 = __half22float2(*reinterpret_cast<__half2*>(&u.y));
        float2 f2 = __half22float2(*reinterpret_cast<__half2*>(&u.z));
        float2 f3 = __half22float2(*reinterpret_cast<__half2*>(&u.w));
        a0 = fmaf(v, f0.x, a0);  a1 = fmaf(v, f0.y, a1);
        a2 = fmaf(v, f1.x, a2);  a3 = fmaf(v, f1.y, a3);
        a4 = fmaf(v, f2.x, a4);  a5 = fmaf(v, f2.y, a5);
        a6 = fmaf(v, f3.x, a6);  a7 = fmaf(v, f3.y, a7);
    }
    float4 o0 = make_float4(fmaxf(a0, 0.f), fmaxf(a1, 0.f),
                            fmaxf(a2, 0.f), fmaxf(a3, 0.f));
    float4 o1 = make_float4(fmaxf(a4, 0.f), fmaxf(a5, 0.f),
                            fmaxf(a6, 0.f), fmaxf(a7, 0.f));
    float4* orow = reinterpret_cast<float4*>(out + (size_t)r * OUT_DIM);
    orow[lane * 2]     = o0;
    orow[lane * 2 + 1] = o1;
}

// ---------------------------------------------------------------------------
// metadata order: feat_rows, feat_cols, feat_vals, adj_rows, adj_cols,
//                 adj_vals, W, n_nodes
// ---------------------------------------------------------------------------
extern "C" void kernel_launch(void* const* d_in, const int* in_sizes, int n_in,
                              void* d_out, int out_size) {
    const int*   feat_rows = (const int*)d_in[0];
    const int*   feat_cols = (const int*)d_in[1];
    const float* feat_vals = (const float*)d_in[2];
    const int*   adj_rows  = (const int*)d_in[3];
    const int*   adj_cols  = (const int*)d_in[4];
    const float* adj_vals  = (const float*)d_in[5];
    const float* W         = (const float*)d_in[6];
    float* out = (float*)d_out;

    init_kernel<<<(N_NODES + 255) / 256, 256>>>(W);
    hist_rank_kernel<<<(NNZ_X + 255) / 256, 256>>>(feat_rows, adj_rows);

    dim3 sg(SCAN_NBLK, 2);
    scan_kernel<<<sg, 256>>>();

    dim3 sc((NNZ_X + 255) / 256, 2);
    scatter_pairs_kernel<<<sc, 256>>>(feat_cols, feat_vals,
                                      adj_cols, adj_vals);

    xw_gather_kernel<<<(N_NODES * 16 + 255) / 256, 256>>>();
    agg_gather_kernel<<<(N_NODES * 16 + 255) / 256, 256>>>(out);
}

// round 11
// speedup vs baseline: 1.0749x; 1.0475x over previous
#include <cuda_runtime.h>
#include <cuda_fp16.h>

#define N_NODES 100000
#define N_FEAT  256
#define OUT_DIM 128
#define NNZ_X   1600000
#define NNZ_A   1600000

#define SCAN_CHUNK 2048          // 256 threads x 8 elems
#define SCAN_NBLK  ((N_NODES + SCAN_CHUNK - 1) / SCAN_CHUNK)   // 49

// ---------------- device scratch (device-code references only) ----------------
__device__ uint4  g_xw4[(size_t)N_NODES * 16];   // xw fp16: row = 256 B = 16 uint4
__device__ __half g_W16[N_FEAT * OUT_DIM];       // fp16 copy of W (64 KB)

__device__ int   g_cnt_f[N_NODES];
__device__ int   g_cnt_a[N_NODES];
__device__ int   g_off_f[N_NODES + 1];
__device__ int   g_off_a[N_NODES + 1];

// packed (row<<15 | rank): row 17 bits (<131072), rank 15 bits (max deg ~50)
__device__ unsigned g_rr_f[NNZ_X];
__device__ unsigned g_rr_a[NNZ_A];

// decoupled-lookback state, PACKED: high32 = flag (0=invalid,1=agg,2=inclusive)
__device__ unsigned long long g_scan_pack[2][SCAN_NBLK];

// packed (col, val-bits) pairs, row-sorted
__device__ int2  g_pair_f[NNZ_X];
__device__ int2  g_pair_a[NNZ_A];

// ---------------------------------------------------------------------------
// 0) zero histograms + reset scan state + convert W to fp16 + static totals
// ---------------------------------------------------------------------------
__global__ void init_kernel(const float* __restrict__ W) {
    int i = blockIdx.x * blockDim.x + threadIdx.x;
    if (i < N_NODES) { g_cnt_f[i] = 0; g_cnt_a[i] = 0; }
    if (i < 2 * SCAN_NBLK) {
        g_scan_pack[i / SCAN_NBLK][i % SCAN_NBLK] = 0ULL;
    }
    if (i < N_FEAT * OUT_DIM) {
        g_W16[i] = __float2half_rn(__ldg(W + i));
    }
    if (i == 0) { g_off_f[N_NODES] = NNZ_X; g_off_a[N_NODES] = NNZ_A; }
}

// ---------------------------------------------------------------------------
// 1) per-side histogram; publish packed (row<<15 | rank).
// ---------------------------------------------------------------------------
__global__ void hist_rank_kernel(const int* __restrict__ rows, int arr) {
    int i = blockIdx.x * blockDim.x + threadIdx.x;
    int* cnt = (arr == 0) ? g_cnt_f : g_cnt_a;
    unsigned* rr = (arr == 0) ? g_rr_f : g_rr_a;
    int n = (arr == 0) ? NNZ_X : NNZ_A;
    if (i >= n) return;
    unsigned r = (unsigned)__ldg(rows + i);
    unsigned rk = (unsigned)atomicAdd(&cnt[r], 1);
    rr[i] = (r << 15) | rk;
}

// ---------------------------------------------------------------------------
// 2) per-side single-pass exclusive scan (decoupled lookback).
// ---------------------------------------------------------------------------
__global__ void scan_kernel(int arr) {
    __shared__ int s[256];
    __shared__ int s_excl;
    const int* cnt = (arr == 0) ? g_cnt_f : g_cnt_a;
    int* off = (arr == 0) ? g_off_f : g_off_a;

    int t = threadIdx.x;
    int bid = blockIdx.x;
    int base = bid * SCAN_CHUNK + t * 8;

    int local[8];
    int sum = 0;
#pragma unroll
    for (int k = 0; k < 8; k++) {
        int idx = base + k;
        local[k] = (idx < N_NODES) ? cnt[idx] : 0;
        sum += local[k];
    }
    s[t] = sum;
    __syncthreads();
    for (int d = 1; d < 256; d <<= 1) {
        int v = (t >= d) ? s[t - d] : 0;
        __syncthreads();
        s[t] += v;
        __syncthreads();
    }
    int block_total = s[255];

    if (t == 0) {
        if (bid == 0) {
            atomicExch(&g_scan_pack[arr][0],
                       (2ULL << 32) | (unsigned)block_total);
            s_excl = 0;
        } else {
            atomicExch(&g_scan_pack[arr][bid],
                       (1ULL << 32) | (unsigned)block_total);
            int running = 0;
            for (int p = bid - 1; p >= 0; p--) {
                unsigned long long pk;
                do { pk = atomicAdd(&g_scan_pack[arr][p], 0ULL); }
                while ((pk >> 32) == 0ULL);
                running += (int)(unsigned)pk;
                if ((pk >> 32) == 2ULL) break;
            }
            atomicExch(&g_scan_pack[arr][bid],
                       (2ULL << 32) | (unsigned)(running + block_total));
            s_excl = running;
        }
    }
    __syncthreads();
    int excl_blk = s_excl;

    int excl_thr = (t == 0) ? 0 : s[t - 1];
    int run = excl_blk + excl_thr;
#pragma unroll
    for (int k = 0; k < 8; k++) {
        int idx = base + k;
        if (idx < N_NODES) { off[idx] = run; run += local[k]; }
    }
}

// ---------------------------------------------------------------------------
// 3) per-side ATOMIC-FREE scatter: pos = off[row] + rank from packed stream.
// ---------------------------------------------------------------------------
__global__ void scatter_pairs_kernel(const int* __restrict__ cols,
                                     const float* __restrict__ vals, int arr) {
    int i = blockIdx.x * blockDim.x + threadIdx.x;
    const unsigned* rr = (arr == 0) ? g_rr_f : g_rr_a;
    const int* off = (arr == 0) ? g_off_f : g_off_a;
    int2* pair = (arr == 0) ? g_pair_f : g_pair_a;
    int n = (arr == 0) ? NNZ_X : NNZ_A;
    if (i >= n) return;
    unsigned pk = rr[i];
    int pos = __ldg(off + (pk >> 15)) + (int)(pk & 0x7FFFu);
    pair[pos] = make_int2(__ldg(cols + i), __float_as_int(__ldg(vals + i)));
}

// ---------------------------------------------------------------------------
// 4) stage 1 gather: xw[r,:] = sum_j val[j] * W16[col[j],:]
// ---------------------------------------------------------------------------
__global__ void xw_gather_kernel() {
    int gtid = blockIdx.x * blockDim.x + threadIdx.x;
    int r    = gtid >> 4;
    int lane = gtid & 15;
    if (r >= N_NODES) return;

    int s = __ldg(g_off_f + r);
    int e = __ldg(g_off_f + r + 1);

    const uint4* W4 = reinterpret_cast<const uint4*>(g_W16);
    float a0 = 0.f, a1 = 0.f, a2 = 0.f, a3 = 0.f;
    float a4 = 0.f, a5 = 0.f, a6 = 0.f, a7 = 0.f;
#pragma unroll 4
    for (int j = s; j < e; j++) {
        int2 p = __ldg(g_pair_f + j);
        float v = __int_as_float(p.y);
        uint4 u = __ldg(W4 + (size_t)p.x * 16 + lane);
        float2 f0 = __half22float2(*reinterpret_cast<__half2*>(&u.x));
        float2 f1 = __half22float2(*reinterpret_cast<__half2*>(&u.y));
        float2 f2 = __half22float2(*reinterpret_cast<__half2*>(&u.z));
        float2 f3 = __half22float2(*reinterpret_cast<__half2*>(&u.w));
        a0 = fmaf(v, f0.x, a0);  a1 = fmaf(v, f0.y, a1);
        a2 = fmaf(v, f1.x, a2);  a3 = fmaf(v, f1.y, a3);
        a4 = fmaf(v, f2.x, a4);  a5 = fmaf(v, f2.y, a5);
        a6 = fmaf(v, f3.x, a6);  a7 = fmaf(v, f3.y, a7);
    }
    __half2 h0 = __floats2half2_rn(a0, a1);
    __half2 h1 = __floats2half2_rn(a2, a3);
    __half2 h2 = __floats2half2_rn(a4, a5);
    __half2 h3 = __floats2half2_rn(a6, a7);
    uint4 u;
    u.x = *reinterpret_cast<unsigned*>(&h0);
    u.y = *reinterpret_cast<unsigned*>(&h1);
    u.z = *reinterpret_cast<unsigned*>(&h2);
    u.w = *reinterpret_cast<unsigned*>(&h3);
    g_xw4[(size_t)r * 16 + lane] = u;
}

// ---------------------------------------------------------------------------
// 5) stage 2 gather + ReLU, half-warp per row.
// ---------------------------------------------------------------------------
__global__ void agg_gather_kernel(float* __restrict__ out) {
    int gtid = blockIdx.x * blockDim.x + threadIdx.x;
    int r    = gtid >> 4;
    int lane = gtid & 15;
    if (r >= N_NODES) return;

    int s = __ldg(g_off_a + r);
    int e = __ldg(g_off_a + r + 1);

    float a0 = 0.f, a1 = 0.f, a2 = 0.f, a3 = 0.f;
    float a4 = 0.f, a5 = 0.f, a6 = 0.f, a7 = 0.f;
#pragma unroll 4
    for (int j = s; j < e; j++) {
        int2 p = __ldg(g_pair_a + j);
        float v = __int_as_float(p.y);
        uint4 u = __ldg(g_xw4 + (size_t)p.x * 16 + lane);
        float2 f0 = __half22float2(*reinterpret_cast<__half2*>(&u.x));
        float2 f1 = __half22float2(*reinterpret_cast<__half2*>(&u.y));
        float2 f2 = __half22float2(*reinterpret_cast<__half2*>(&u.z));
        float2 f3 = __half22float2(*reinterpret_cast<__half2*>(&u.w));
        a0 = fmaf(v, f0.x, a0);  a1 = fmaf(v, f0.y, a1);
        a2 = fmaf(v, f1.x, a2);  a3 = fmaf(v, f1.y, a3);
        a4 = fmaf(v, f2.x, a4);  a5 = fmaf(v, f2.y, a5);
        a6 = fmaf(v, f3.x, a6);  a7 = fmaf(v, f3.y, a7);
    }
    float4 o0 = make_float4(fmaxf(a0, 0.f), fmaxf(a1, 0.f),
                            fmaxf(a2, 0.f), fmaxf(a3, 0.f));
    float4 o1 = make_float4(fmaxf(a4, 0.f), fmaxf(a5, 0.f),
                            fmaxf(a6, 0.f), fmaxf(a7, 0.f));
    float4* orow = reinterpret_cast<float4*>(out + (size_t)r * OUT_DIM);
    orow[lane * 2]     = o0;
    orow[lane * 2 + 1] = o1;
}

// ---------------------------------------------------------------------------
// Two-stream fork/join: adj CSR chain overlaps the feat chain.
// metadata order: feat_rows, feat_cols, feat_vals, adj_rows, adj_cols,
//                 adj_vals, W, n_nodes
// ---------------------------------------------------------------------------
extern "C" void kernel_launch(void* const* d_in, const int* in_sizes, int n_in,
                              void* d_out, int out_size) {
    const int*   feat_rows = (const int*)d_in[0];
    const int*   feat_cols = (const int*)d_in[1];
    const float* feat_vals = (const float*)d_in[2];
    const int*   adj_rows  = (const int*)d_in[3];
    const int*   adj_cols  = (const int*)d_in[4];
    const float* adj_vals  = (const float*)d_in[5];
    const float* W         = (const float*)d_in[6];
    float* out = (float*)d_out;

    cudaStream_t s2;
    cudaStreamCreateWithFlags(&s2, cudaStreamNonBlocking);
    cudaEvent_t e0, e1;
    cudaEventCreateWithFlags(&e0, cudaEventDisableTiming);
    cudaEventCreateWithFlags(&e1, cudaEventDisableTiming);

    const int nnz_blocks = (NNZ_X + 255) / 256;

    // common init on the main (captured) stream
    init_kernel<<<(N_NODES + 255) / 256, 256>>>(W);

    // fork adj chain onto s2
    cudaEventRecord(e0, 0);
    cudaStreamWaitEvent(s2, e0, 0);

    // feat chain (main stream)
    hist_rank_kernel<<<nnz_blocks, 256>>>(feat_rows, 0);
    scan_kernel<<<SCAN_NBLK, 256>>>(0);
    scatter_pairs_kernel<<<nnz_blocks, 256>>>(feat_cols, feat_vals, 0);
    xw_gather_kernel<<<(N_NODES * 16 + 255) / 256, 256>>>();

    // adj chain (s2)
    hist_rank_kernel<<<nnz_blocks, 256, 0, s2>>>(adj_rows, 1);
    scan_kernel<<<SCAN_NBLK, 256, 0, s2>>>(1);
    scatter_pairs_kernel<<<nnz_blocks, 256, 0, s2>>>(adj_cols, adj_vals, 1);
    cudaEventRecord(e1, s2);

    // join and final stage
    cudaStreamWaitEvent(0, e1, 0);
    agg_gather_kernel<<<(N_NODES * 16 + 255) / 256, 256>>>(out);
}